// round 2
// baseline (speedup 1.0000x reference)
#include <cuda_runtime.h>
#include <math.h>

#define T_STEPS   8192
#define N_RES     2048
#define DIN       64
#define DOUT      64
#define NNZ_CAP   384          // 32 lanes x 12 slots
#define SLOTS     12           // nnz slots per lane
#define GRID_MAIN 128
#define ROWS_PER_CTA 16
#define THREADS_MAIN 512
#define LEAK      0.3f
#define ONE_MINUS_LEAK 0.7f
#define NOISE_SCL 0.01f

// ---- device scratch (static; no allocation anywhere) ----
__device__ float    g_vals[(size_t)N_RES * NNZ_CAP];
__device__ int      g_cols[(size_t)N_RES * NNZ_CAP];
__device__ float    g_states[(size_t)T_STEPS * N_RES];       // 64 MB
__device__ __align__(16) unsigned g_flags[GRID_MAIN];        // packed: 512 B

// ---- reset barrier flags (runs first on every graph replay) ----
__global__ void k_init() {
    int i = threadIdx.x;
    if (i < GRID_MAIN) g_flags[i] = 0u;
}

// ---- build bank-aware padded sparse rows: one warp per row ----
// lane l owns columns with col%32 == l -> conflict-free smem gathers.
// storage: g_vals[row*384 + l*12 + k]  (3 float4 per lane, 16B aligned)
#define SPILL_CAP 128
__global__ void __launch_bounds__(256) k_build(const float* __restrict__ W) {
    __shared__ float sv[8][SPILL_CAP];
    __shared__ int   sc[8][SPILL_CAP];
    __shared__ int   sn[8];
    int wwarp = threadIdx.x >> 5;
    int lane  = threadIdx.x & 31;
    int row   = blockIdx.x * 8 + wwarp;
    if (row >= N_RES) return;
    if (lane == 0) sn[wwarp] = 0;
    __syncwarp();

    const float* wr = W + (size_t)row * N_RES;
    float* vd = g_vals + (size_t)row * NNZ_CAP;
    int*   cd = g_cols + (size_t)row * NNZ_CAP;

    int cnt = 0;
    for (int base = 0; base < N_RES / 32; base++) {
        int col = base * 32 + lane;          // coalesced read
        float v = wr[col];
        if (v != 0.0f) {
            if (cnt < SLOTS) { vd[lane * SLOTS + cnt] = v; cd[lane * SLOTS + cnt] = col; cnt++; }
            else {
                int p = atomicAdd(&sn[wwarp], 1);
                if (p < SPILL_CAP) { sv[wwarp][p] = v; sc[wwarp][p] = col; }
            }
        }
    }
    __syncwarp();
    // distribute spills into free slots via warp prefix sum
    int freecnt = SLOTS - cnt;
    int pfx = freecnt;
    #pragma unroll
    for (int o = 1; o < 32; o <<= 1) {
        int nv = __shfl_up_sync(0xffffffffu, pfx, o);
        if (lane >= o) pfx += nv;
    }
    int excl = pfx - freecnt;
    int ns = sn[wwarp]; if (ns > SPILL_CAP) ns = SPILL_CAP;
    for (int k = 0; k < freecnt; k++) {
        int idx = excl + k;
        if (idx < ns) { vd[lane * SLOTS + cnt + k] = sv[wwarp][idx]; cd[lane * SLOTS + cnt + k] = sc[wwarp][idx]; }
        else          { vd[lane * SLOTS + cnt + k] = 0.0f;           cd[lane * SLOTS + cnt + k] = lane; } // 0*s[lane], bank=lane
    }
}

// ---- persistent recurrence: 128 CTAs, low-traffic flag barrier per step ----
__global__ void __launch_bounds__(THREADS_MAIN, 1)
k_reservoir(const float* __restrict__ u,
            const float* __restrict__ noise,
            const float* __restrict__ W_in) {
    __shared__ float s_smem[N_RES];
    __shared__ float u_s[2][DIN];
    __shared__ __align__(16) float stage[ROWS_PER_CTA];

    const int tid  = threadIdx.x;
    const int lane = tid & 31;
    const int w    = tid >> 5;
    const int row  = blockIdx.x * ROWS_PER_CTA + w;

    // park this row's bank-aligned sparse slice in registers
    float4 v4[3]; int4 c4[3];
    {
        const float4* vp = (const float4*)(g_vals + (size_t)row * NNZ_CAP + lane * SLOTS);
        const int4*   cp = (const int4*)  (g_cols + (size_t)row * NNZ_CAP + lane * SLOTS);
        #pragma unroll
        for (int c = 0; c < 3; c++) { v4[c] = vp[c]; c4[c] = cp[c]; }
    }
    const float win0 = W_in[row * DIN + lane];
    const float win1 = W_in[row * DIN + 32 + lane];

    for (int i = tid; i < N_RES; i += THREADS_MAIN) s_smem[i] = 0.0f;
    if (tid < DIN) u_s[0][tid] = u[tid];
    float noise_cur = noise[row];
    float noise_next = 0.0f;
    __syncthreads();

    for (int t = 0; t < T_STEPS; t++) {
        const int buf = t & 1;
        const int tn  = (t + 1 < T_STEPS) ? t + 1 : t;

        // prefetch next step inputs
        if (tid < DIN) u_s[buf ^ 1][tid] = u[tn * DIN + tid];
        if (lane == 0) noise_next = __ldcs(&noise[(size_t)tn * N_RES + row]);

        // drive + conflict-free sparse gathers
        float acc = fmaf(win0, u_s[buf][lane], win1 * u_s[buf][lane + 32]);
        #pragma unroll
        for (int c = 0; c < 3; c++) {
            acc = fmaf(v4[c].x, s_smem[c4[c].x], acc);
            acc = fmaf(v4[c].y, s_smem[c4[c].y], acc);
            acc = fmaf(v4[c].z, s_smem[c4[c].z], acc);
            acc = fmaf(v4[c].w, s_smem[c4[c].w], acc);
        }
        #pragma unroll
        for (int o = 16; o; o >>= 1) acc += __shfl_xor_sync(0xffffffffu, acc, o);

        if (lane == 0) {
            acc += NOISE_SCL * noise_cur;
            stage[w] = ONE_MINUS_LEAK * s_smem[row] + LEAK * tanhf(acc);
        }
        noise_cur = noise_next;
        __syncthreads();                 // stage complete; all s_smem reads done

        const unsigned target = (unsigned)(t + 1);
        if (tid == 0) {
            // publish 16 contiguous floats (64 B) then release the flag.
            // release by the SAME thread orders the data stores before the flag.
            float4* dst = (float4*)(g_states + (size_t)t * N_RES + blockIdx.x * ROWS_PER_CTA);
            const float4* sg = (const float4*)stage;
            dst[0] = sg[0]; dst[1] = sg[1]; dst[2] = sg[2]; dst[3] = sg[3];
            asm volatile("st.release.gpu.u32 [%0], %1;"
                         :: "l"(&g_flags[blockIdx.x]), "r"(target) : "memory");
        }
        // warp 0 polls all 128 flags: 32 lanes x one v4 load (4 flags each)
        if (w == 0) {
            const unsigned* fp = &g_flags[lane * 4];
            unsigned notdone;
            do {
                uint4 f;
                asm volatile("ld.volatile.v4.u32 {%0,%1,%2,%3}, [%4];"
                             : "=r"(f.x), "=r"(f.y), "=r"(f.z), "=r"(f.w)
                             : "l"(fp) : "memory");
                notdone = (unsigned)(f.x < target) | (unsigned)(f.y < target) |
                          (unsigned)(f.z < target) | (unsigned)(f.w < target);
            } while (__any_sync(0xffffffffu, notdone));
        }
        __syncthreads();

        // reload full new state (L2-fresh; .cg bypasses L1 so release ordering holds)
        const float4* sp = (const float4*)(g_states + (size_t)t * N_RES);
        float4 sv = __ldcg((float4*)&sp[tid]);
        ((float4*)s_smem)[tid] = sv;
        __syncthreads();
    }
}

// ---- readout GEMM: out[T,64] = states @ w_out^T + b_out ----
// 32x64 tile, 128 threads, 4x4 microtile, grid 256 (2 CTAs/SM)
#define KC 32
__global__ void __launch_bounds__(128, 2)
k_out(const float* __restrict__ w_out, const float* __restrict__ b_out,
      float* __restrict__ out) {
    __shared__ float sA[32][KC];
    __shared__ float sB[64][KC];
    const int tid = threadIdx.x;
    const int tx  = tid & 15;      // 4 output cols each
    const int ty  = tid >> 4;      // 0..7 -> 4 output rows each
    const int t0  = blockIdx.x * 32;

    float acc[4][4];
    #pragma unroll
    for (int i = 0; i < 4; i++)
        #pragma unroll
        for (int j = 0; j < 4; j++) acc[i][j] = 0.0f;

    for (int k0 = 0; k0 < N_RES; k0 += KC) {
        #pragma unroll
        for (int it = 0; it < 2; it++) {          // sA: 256 float4 slots
            int idx = tid + it * 128;
            int r = idx >> 3, kk = (idx & 7) * 4;
            *(float4*)&sA[r][kk] = *(const float4*)&g_states[(size_t)(t0 + r) * N_RES + k0 + kk];
        }
        #pragma unroll
        for (int it = 0; it < 4; it++) {          // sB: 512 float4 slots
            int idx = tid + it * 128;
            int r = idx >> 3, kk = (idx & 7) * 4;
            *(float4*)&sB[r][kk] = *(const float4*)&w_out[(size_t)r * N_RES + k0 + kk];
        }
        __syncthreads();
        #pragma unroll
        for (int kk = 0; kk < KC; kk += 4) {
            float4 a[4], b[4];
            #pragma unroll
            for (int i = 0; i < 4; i++) a[i] = *(const float4*)&sA[ty * 4 + i][kk];
            #pragma unroll
            for (int j = 0; j < 4; j++) b[j] = *(const float4*)&sB[tx * 4 + j][kk];
            #pragma unroll
            for (int i = 0; i < 4; i++)
                #pragma unroll
                for (int j = 0; j < 4; j++) {
                    acc[i][j] = fmaf(a[i].x, b[j].x, acc[i][j]);
                    acc[i][j] = fmaf(a[i].y, b[j].y, acc[i][j]);
                    acc[i][j] = fmaf(a[i].z, b[j].z, acc[i][j]);
                    acc[i][j] = fmaf(a[i].w, b[j].w, acc[i][j]);
                }
        }
        __syncthreads();
    }
    #pragma unroll
    for (int i = 0; i < 4; i++)
        #pragma unroll
        for (int j = 0; j < 4; j++)
            out[(size_t)(t0 + ty * 4 + i) * DOUT + tx * 4 + j] = acc[i][j] + b_out[tx * 4 + j];
}

extern "C" void kernel_launch(void* const* d_in, const int* in_sizes, int n_in,
                              void* d_out, int out_size) {
    const float* u     = (const float*)d_in[0];
    const float* noise = (const float*)d_in[1];
    const float* W_in  = (const float*)d_in[2];
    const float* W     = (const float*)d_in[3];
    const float* w_out = (const float*)d_in[4];
    const float* b_out = (const float*)d_in[5];
    float* out = (float*)d_out;

    k_init<<<1, 128>>>();
    k_build<<<N_RES / 8, 256>>>(W);
    k_reservoir<<<GRID_MAIN, THREADS_MAIN>>>(u, noise, W_in);
    k_out<<<T_STEPS / 32, 128>>>(w_out, b_out, out);
}

// round 4
// speedup vs baseline: 2.8963x; 2.8963x over previous
#include <cuda_runtime.h>
#include <math.h>

#define T_STEPS   8192
#define N_RES     2048
#define DIN       64
#define DOUT      64
#define NNZ_CAP   384          // 32 lanes x 12 slots (mean nnz/row ~205)
#define SLOTS     12
#define GRID_MAIN 64
#define ROWS_PER_CTA 32        // 2048 / 64
#define THREADS_MAIN 1024      // 32 warps, 1 warp per row
#define FLAG_STRIDE 32         // 32 uints = 128 B  -> one L2 line per flag
#define LEAK      0.3f
#define ONE_MINUS_LEAK 0.7f
#define NOISE_SCL 0.01f

// ---- device scratch (static; no allocation anywhere) ----
__device__ float    g_vals[(size_t)N_RES * NNZ_CAP];
__device__ int      g_cols[(size_t)N_RES * NNZ_CAP];
__device__ float    g_states[(size_t)T_STEPS * N_RES];           // 64 MB
__device__ __align__(128) unsigned g_flags[GRID_MAIN * FLAG_STRIDE]; // 8 KB, 1 line/flag

// ---- reset barrier flags (runs first on every graph replay) ----
__global__ void k_init() {
    int i = blockIdx.x * blockDim.x + threadIdx.x;
    if (i < GRID_MAIN * FLAG_STRIDE) g_flags[i] = 0u;
}

// ---- build bank-aware padded sparse rows: one warp per row ----
// lane l primarily owns columns with col%32 == l -> conflict-free smem gathers;
// overflow entries are redistributed into other lanes' free slots.
#define SPILL_CAP 128
__global__ void __launch_bounds__(256) k_build(const float* __restrict__ W) {
    __shared__ float sv[8][SPILL_CAP];
    __shared__ int   sc[8][SPILL_CAP];
    __shared__ int   sn[8];
    int wwarp = threadIdx.x >> 5;
    int lane  = threadIdx.x & 31;
    int row   = blockIdx.x * 8 + wwarp;
    if (row >= N_RES) return;
    if (lane == 0) sn[wwarp] = 0;
    __syncwarp();

    const float* wr = W + (size_t)row * N_RES;
    float* vd = g_vals + (size_t)row * NNZ_CAP;
    int*   cd = g_cols + (size_t)row * NNZ_CAP;

    int cnt = 0;
    for (int base = 0; base < N_RES / 32; base++) {
        int col = base * 32 + lane;
        float v = wr[col];
        if (v != 0.0f) {
            if (cnt < SLOTS) { vd[lane * SLOTS + cnt] = v; cd[lane * SLOTS + cnt] = col; cnt++; }
            else {
                int p = atomicAdd(&sn[wwarp], 1);
                if (p < SPILL_CAP) { sv[wwarp][p] = v; sc[wwarp][p] = col; }
            }
        }
    }
    __syncwarp();
    int freecnt = SLOTS - cnt;
    int pfx = freecnt;
    #pragma unroll
    for (int o = 1; o < 32; o <<= 1) {
        int nv = __shfl_up_sync(0xffffffffu, pfx, o);
        if (lane >= o) pfx += nv;
    }
    int excl = pfx - freecnt;
    int ns = sn[wwarp]; if (ns > SPILL_CAP) ns = SPILL_CAP;
    for (int k = 0; k < freecnt; k++) {
        int idx = excl + k;
        if (idx < ns) { vd[lane * SLOTS + cnt + k] = sv[wwarp][idx]; cd[lane * SLOTS + cnt + k] = sc[wwarp][idx]; }
        else          { vd[lane * SLOTS + cnt + k] = 0.0f;           cd[lane * SLOTS + cnt + k] = lane; }
    }
}

// ---- persistent recurrence: 64 CTAs, line-isolated flags, warp-0-only polling ----
__global__ void __launch_bounds__(THREADS_MAIN, 1)
k_reservoir(const float* __restrict__ u,
            const float* __restrict__ noise,
            const float* __restrict__ W_in) {
    __shared__ float s_smem[N_RES];
    __shared__ float u_s[2][DIN];
    __shared__ __align__(16) float stage[ROWS_PER_CTA];

    const int tid  = threadIdx.x;
    const int lane = tid & 31;
    const int w    = tid >> 5;
    const int row  = blockIdx.x * ROWS_PER_CTA + w;

    // park this row's bank-aligned sparse slice in registers for the whole run
    float4 v4[3]; int4 c4[3];
    {
        const float4* vp = (const float4*)(g_vals + (size_t)row * NNZ_CAP + lane * SLOTS);
        const int4*   cp = (const int4*)  (g_cols + (size_t)row * NNZ_CAP + lane * SLOTS);
        #pragma unroll
        for (int c = 0; c < 3; c++) { v4[c] = vp[c]; c4[c] = cp[c]; }
    }
    const float win0 = W_in[row * DIN + lane];
    const float win1 = W_in[row * DIN + 32 + lane];

    for (int i = tid; i < N_RES; i += THREADS_MAIN) s_smem[i] = 0.0f;
    if (tid < DIN) u_s[0][tid] = u[tid];
    float noise_cur = noise[row];
    float noise_next = 0.0f;
    __syncthreads();

    for (int t = 0; t < T_STEPS; t++) {
        const int buf = t & 1;
        const int tn  = (t + 1 < T_STEPS) ? t + 1 : t;

        // prefetch next step inputs (hidden behind compute + barrier)
        if (tid < DIN) u_s[buf ^ 1][tid] = __ldg(&u[tn * DIN + tid]);
        if (lane == 0) noise_next = __ldcs(&noise[(size_t)tn * N_RES + row]);

        // drive + conflict-free sparse gathers
        float acc = fmaf(win0, u_s[buf][lane], win1 * u_s[buf][lane + 32]);
        #pragma unroll
        for (int c = 0; c < 3; c++) {
            acc = fmaf(v4[c].x, s_smem[c4[c].x], acc);
            acc = fmaf(v4[c].y, s_smem[c4[c].y], acc);
            acc = fmaf(v4[c].z, s_smem[c4[c].z], acc);
            acc = fmaf(v4[c].w, s_smem[c4[c].w], acc);
        }
        #pragma unroll
        for (int o = 16; o; o >>= 1) acc += __shfl_xor_sync(0xffffffffu, acc, o);

        if (lane == 0) {
            acc += NOISE_SCL * noise_cur;
            stage[w] = ONE_MINUS_LEAK * s_smem[row] + LEAK * tanhf(acc);
        }
        noise_cur = noise_next;
        __syncthreads();                 // stage ready; all s_smem reads done

        const unsigned target = (unsigned)(t + 1);
        if (tid == 0) {
            // tid0 publishes 32 contiguous floats (128 B) then releases its flag.
            // Same-thread release orders the data stores before the flag: no fence.
            float4* dst = (float4*)(g_states + (size_t)t * N_RES + blockIdx.x * ROWS_PER_CTA);
            const float4* sg = (const float4*)stage;
            #pragma unroll
            for (int i = 0; i < 8; i++) dst[i] = sg[i];
            asm volatile("st.release.gpu.u32 [%0], %1;"
                         :: "l"(&g_flags[blockIdx.x * FLAG_STRIDE]), "r"(target) : "memory");
        }
        // warp 0 only: lane polls CTA lane and CTA lane+32 (each flag = own L2 line)
        if (w == 0) {
            const unsigned* f0 = &g_flags[lane * FLAG_STRIDE];
            const unsigned* f1 = &g_flags[(lane + 32) * FLAG_STRIDE];
            unsigned notdone;
            do {
                unsigned a, b;
                asm volatile("ld.volatile.global.u32 %0, [%1];" : "=r"(a) : "l"(f0) : "memory");
                asm volatile("ld.volatile.global.u32 %0, [%1];" : "=r"(b) : "l"(f1) : "memory");
                notdone = (unsigned)(a < target) | (unsigned)(b < target);
            } while (__any_sync(0xffffffffu, notdone));
        }
        __syncthreads();

        // reload full new state (L2-fresh; .cg bypasses L1 so release ordering holds)
        const float2* sp = (const float2*)(g_states + (size_t)t * N_RES);
        float2 sv = __ldcg((float2*)&sp[tid]);
        ((float2*)s_smem)[tid] = sv;
        __syncthreads();
    }
}

// ---- readout GEMM: out[T,64] = states @ w_out^T + b_out ----
#define KC 32
__global__ void __launch_bounds__(128, 2)
k_out(const float* __restrict__ w_out, const float* __restrict__ b_out,
      float* __restrict__ out) {
    __shared__ float sA[32][KC];
    __shared__ float sB[64][KC];
    const int tid = threadIdx.x;
    const int tx  = tid & 15;
    const int ty  = tid >> 4;
    const int t0  = blockIdx.x * 32;

    float acc[4][4];
    #pragma unroll
    for (int i = 0; i < 4; i++)
        #pragma unroll
        for (int j = 0; j < 4; j++) acc[i][j] = 0.0f;

    for (int k0 = 0; k0 < N_RES; k0 += KC) {
        #pragma unroll
        for (int it = 0; it < 2; it++) {
            int idx = tid + it * 128;
            int r = idx >> 3, kk = (idx & 7) * 4;
            *(float4*)&sA[r][kk] = *(const float4*)&g_states[(size_t)(t0 + r) * N_RES + k0 + kk];
        }
        #pragma unroll
        for (int it = 0; it < 4; it++) {
            int idx = tid + it * 128;
            int r = idx >> 3, kk = (idx & 7) * 4;
            *(float4*)&sB[r][kk] = *(const float4*)&w_out[(size_t)r * N_RES + k0 + kk];
        }
        __syncthreads();
        #pragma unroll
        for (int kk = 0; kk < KC; kk += 4) {
            float4 a[4], b[4];
            #pragma unroll
            for (int i = 0; i < 4; i++) a[i] = *(const float4*)&sA[ty * 4 + i][kk];
            #pragma unroll
            for (int j = 0; j < 4; j++) b[j] = *(const float4*)&sB[tx * 4 + j][kk];
            #pragma unroll
            for (int i = 0; i < 4; i++)
                #pragma unroll
                for (int j = 0; j < 4; j++) {
                    acc[i][j] = fmaf(a[i].x, b[j].x, acc[i][j]);
                    acc[i][j] = fmaf(a[i].y, b[j].y, acc[i][j]);
                    acc[i][j] = fmaf(a[i].z, b[j].z, acc[i][j]);
                    acc[i][j] = fmaf(a[i].w, b[j].w, acc[i][j]);
                }
        }
        __syncthreads();
    }
    #pragma unroll
    for (int i = 0; i < 4; i++)
        #pragma unroll
        for (int j = 0; j < 4; j++)
            out[(size_t)(t0 + ty * 4 + i) * DOUT + tx * 4 + j] = acc[i][j] + b_out[tx * 4 + j];
}

extern "C" void kernel_launch(void* const* d_in, const int* in_sizes, int n_in,
                              void* d_out, int out_size) {
    const float* u     = (const float*)d_in[0];
    const float* noise = (const float*)d_in[1];
    const float* W_in  = (const float*)d_in[2];
    const float* W     = (const float*)d_in[3];
    const float* w_out = (const float*)d_in[4];
    const float* b_out = (const float*)d_in[5];
    float* out = (float*)d_out;

    k_init<<<2, 1024>>>();
    k_build<<<N_RES / 8, 256>>>(W);
    k_reservoir<<<GRID_MAIN, THREADS_MAIN>>>(u, noise, W_in);
    k_out<<<T_STEPS / 32, 128>>>(w_out, b_out, out);
}